// round 17
// baseline (speedup 1.0000x reference)
#include <cuda_runtime.h>
#include <cuda_bf16.h>
#include <math.h>
#include <stdint.h>

// ---------------------------------------------------------------------------
// Problem constants
// ---------------------------------------------------------------------------
#define B        8
#define CIN      15          // 3*5 after reshape
#define C1       64
#define H0       512
#define W0       512
#define H1       256
#define W1       256
#define C2       128
#define H2       128
#define W2       128
#define NE       3

// NHWC padded activation for head1 (conv2 out): [B][130][132][128] bf16 x2
#define AR 130
#define AW 132
// NHWC-16 even/odd deinterleaved padded input (conv1 + gating MMA):
// per (b,row): 520 entries x 16 ch bf16.  row = iy+3 (0..516, alloc 520).
#define XNW 520
// NHWC-64 even/odd deinterleaved conv1 output (conv2 MMA input):
// per (b,row): 260 entries x 64 ch bf16 x2.  row = iy+1 (0..256, alloc 258).
//   even: pos = px/2 (0..127); odd: pos = 129 + (px-1)/2, o=-1 at pos 128.
#define C1R 258
#define C1WP 260

// ---------------------------------------------------------------------------
// Device scratch
// ---------------------------------------------------------------------------
__device__ __align__(16) float d_gbuf  [(long)B*C1*H1*W1];
__device__ __align__(16) __nv_bfloat16 d_c1out_h[(long)B*C1R*C1WP*C1];
__device__ __align__(16) __nv_bfloat16 d_c1out_l[(long)B*C1R*C1WP*C1];
__device__ __align__(16) __nv_bfloat16 d_xnh_h[(long)B*520*XNW*16];
__device__ __align__(16) __nv_bfloat16 d_xnh_l[(long)B*520*XNW*16];
__device__ __align__(16) __nv_bfloat16 d_w1c_h[(NE+1)*7*7*C1*16];   // slot NE = gating
__device__ __align__(16) __nv_bfloat16 d_w1c_l[(NE+1)*7*7*C1*16];
__device__ __align__(16) __nv_bfloat16 d_w2c_h[NE*3*3*C2*C1];
__device__ __align__(16) __nv_bfloat16 d_w2c_l[NE*3*3*C2*C1];
__device__ __align__(16) __nv_bfloat16 d_act_hi[(long)B*AR*AW*C2];
__device__ __align__(16) __nv_bfloat16 d_act_lo[(long)B*AR*AW*C2];
__device__ __align__(16) __nv_bfloat16 d_w1h[NE*9*C2*C2];
__device__ __align__(16) __nv_bfloat16 d_w1l[NE*9*C2*C2];
__device__ __align__(16) float d_ebuf3 [(long)B*C2*H2*W2];
__device__ float d_pooled[B*C1];
__device__ int   d_eidx[B];

// ---------------------------------------------------------------------------
// Warp-level bf16 MMA + ldmatrix (baseline PTX ISA)
// ---------------------------------------------------------------------------
__device__ __forceinline__ void mma_bf16(float* d,
                                         uint32_t a0, uint32_t a1,
                                         uint32_t a2, uint32_t a3,
                                         uint32_t b0, uint32_t b1)
{
    asm volatile(
        "mma.sync.aligned.m16n8k16.row.col.f32.bf16.bf16.f32 "
        "{%0,%1,%2,%3}, {%4,%5,%6,%7}, {%8,%9}, {%0,%1,%2,%3};"
        : "+f"(d[0]), "+f"(d[1]), "+f"(d[2]), "+f"(d[3])
        : "r"(a0), "r"(a1), "r"(a2), "r"(a3), "r"(b0), "r"(b1));
}
__device__ __forceinline__ void ldm_x4(uint32_t* r, uint32_t addr)
{
    asm volatile("ldmatrix.sync.aligned.m8n8.x4.shared.b16 {%0,%1,%2,%3}, [%4];"
                 : "=r"(r[0]), "=r"(r[1]), "=r"(r[2]), "=r"(r[3]) : "r"(addr));
}
__device__ __forceinline__ void ldm_x2(uint32_t& r0, uint32_t& r1, uint32_t addr)
{
    asm volatile("ldmatrix.sync.aligned.m8n8.x2.shared.b16 {%0,%1}, [%2];"
                 : "=r"(r0), "=r"(r1) : "r"(addr));
}
__device__ __forceinline__ uint32_t smem_u32(const void* p) {
    uint32_t a;
    asm("{ .reg .u64 t; cvta.to.shared.u64 t, %1; cvt.u32.u64 %0, t; }"
        : "=r"(a) : "l"(p));
    return a;
}
// split two floats into packed bf16 hi-pair and lo-residual pair
__device__ __forceinline__ void split2(float a, float b,
                                       uint32_t& hi, uint32_t& lo)
{
    const __nv_bfloat16 ha = __float2bfloat16(a);
    const __nv_bfloat16 hb = __float2bfloat16(b);
    const __nv_bfloat16 la = __float2bfloat16(a - __bfloat162float(ha));
    const __nv_bfloat16 lb = __float2bfloat16(b - __bfloat162float(hb));
    hi = (uint32_t)__bfloat16_as_ushort(ha)
       | ((uint32_t)__bfloat16_as_ushort(hb) << 16);
    lo = (uint32_t)__bfloat16_as_ushort(la)
       | ((uint32_t)__bfloat16_as_ushort(lb) << 16);
}

// ---------------------------------------------------------------------------
// Kernel 0: prep — layout transforms (one launch)
// ---------------------------------------------------------------------------
#define PREP_XN   (B*520)                // NHWC-16 input rows
#define PREP_C1H  (PREP_XN + B)          // c1out halos
#define PREP_ACT  (PREP_C1H + B)         // act_hi/lo halos
#define PREP_W    (PREP_ACT + NE*9)      // head1 weight split
#define PREP_W1   (PREP_W + (NE+1)*7)    // conv1 weight split
#define PREP_W2   (PREP_W1 + NE*3)       // conv2 weight split

__global__ void __launch_bounds__(256)
prep_kernel(const float* __restrict__ x,
            const float* __restrict__ e_hw1,
            const float* __restrict__ e_conv1,
            const float* __restrict__ g_conv_w,
            const float* __restrict__ e_conv2)
{
    const int blk = blockIdx.x;
    const int t   = threadIdx.x;
    if (blk < PREP_XN) {
        // NHWC-16 deinterleaved padded input, bf16 hi/lo
        const int bb  = blk / 520;
        const int row = blk - bb * 520;
        const int iy  = row - 3;
        const bool rowok = (unsigned)iy < (unsigned)H0;
        __nv_bfloat16* H = d_xnh_h + (long)blk * (XNW * 16);
        __nv_bfloat16* L = d_xnh_l + (long)blk * (XNW * 16);
        for (int c = t; c < XNW; c += 256) {
            const int ix = (c < 260) ? (2 * c - 2) : (2 * c - 523);
            const bool ok = rowok && (unsigned)ix < (unsigned)W0;
            __align__(16) __nv_bfloat16 h16[16], l16[16];
#pragma unroll
            for (int ch = 0; ch < 16; ch++) {
                float v = 0.f;
                if (ok && ch < CIN)
                    v = x[((long)(bb * CIN + ch)) * (H0 * W0) + (long)iy * W0 + ix];
                const __nv_bfloat16 h = __float2bfloat16(v);
                h16[ch] = h;
                l16[ch] = __float2bfloat16(v - __bfloat162float(h));
            }
            *(uint4*)(H + c * 16)     = *(const uint4*)h16;
            *(uint4*)(H + c * 16 + 8) = *(const uint4*)(h16 + 8);
            *(uint4*)(L + c * 16)     = *(const uint4*)l16;
            *(uint4*)(L + c * 16 + 8) = *(const uint4*)(l16 + 8);
        }
    } else if (blk < PREP_C1H) {
        // c1out halos: row 0 full; odd o=-1 column (pos 128) rows 1..256
        const int bb = blk - PREP_XN;
        const uint4 z = make_uint4(0, 0, 0, 0);
        for (int pl = 0; pl < 2; pl++) {
            __nv_bfloat16* A = pl ? d_c1out_l : d_c1out_h;
            uint4* r0 = (uint4*)(A + (long)(bb * C1R) * C1WP * C1);
            for (int i = t; i < C1WP * C1 / 8; i += 256) r0[i] = z;
            for (int i = t; i < 256 * 8; i += 256) {
                const int row = 1 + (i >> 3);
                const int ch  = i & 7;
                *((uint4*)(A + ((long)(bb * C1R + row) * C1WP + 128) * C1) + ch) = z;
            }
        }
    } else if (blk < PREP_ACT) {
        const int bb = blk - PREP_C1H;
        const uint4 z = make_uint4(0, 0, 0, 0);
        for (int pl = 0; pl < 2; pl++) {
            __nv_bfloat16* A = pl ? d_act_lo : d_act_hi;
            uint4* r0 = (uint4*)(A + ((long)bb * AR + 0) * AW * C2);
            uint4* r1 = (uint4*)(A + ((long)bb * AR + 129) * AW * C2);
            for (int i = t; i < AW * C2 / 8; i += 256) { r0[i] = z; r1[i] = z; }
            for (int i = t; i < 128 * 2 * 16; i += 256) {
                const int py  = 1 + (i >> 5);
                const int rem = i & 31;
                const int px  = (rem & 16) ? 129 : 0;
                const int ch  = rem & 15;
                *((uint4*)(A + (((long)bb * AR + py) * AW + px) * C2) + ch) = z;
            }
        }
    } else if (blk < PREP_W) {
        // head1 weight split: d_w1{h,l}[e][s][oc][ic]
        const int ws = blk - PREP_ACT;
        const int e  = ws / 9;
        const int s  = ws - e * 9;
        __nv_bfloat16* WH = d_w1h + (long)ws * (C2 * C2);
        __nv_bfloat16* WL = d_w1l + (long)ws * (C2 * C2);
        for (int i = t; i < C2 * C2; i += 256) {
            const int oc = i >> 7, ic = i & 127;
            const float w = e_hw1[(((long)e * C2 + oc) * C2 + ic) * 9 + s];
            const __nv_bfloat16 h = __float2bfloat16(w);
            WH[i] = h;
            WL[i] = __float2bfloat16(w - __bfloat162float(h));
        }
    } else if (blk < PREP_W1) {
        // conv1 weight split: d_w1c[slot][ky][kx*64+oc][ch16]
        const int ws = blk - PREP_W;           // 0..(NE+1)*7-1
        const int e  = ws / 7;                 // e==NE -> gating
        const int ky = ws - e * 7;
        __nv_bfloat16* WH = d_w1c_h + (long)ws * (7 * C1 * 16);
        __nv_bfloat16* WL = d_w1c_l + (long)ws * (7 * C1 * 16);
        const float* src = (e < NE) ? (e_conv1 + (long)e * C1 * CIN * 49)
                                    : g_conv_w;
        for (int i = t; i < 7 * C1 * 16; i += 256) {
            const int kx = i >> 10;
            const int rem = i & 1023;
            const int oc = rem >> 4, ch = rem & 15;
            float w = 0.f;
            if (ch < CIN)
                w = src[(((long)oc * CIN + ch) * 49) + ky * 7 + kx];
            const __nv_bfloat16 h = __float2bfloat16(w);
            WH[i] = h;
            WL[i] = __float2bfloat16(w - __bfloat162float(h));
        }
    } else {
        // conv2 weight split: d_w2c[e][ky][kx*128+oc][ch64]
        const int ws = blk - PREP_W1;          // 0..NE*3-1
        const int e  = ws / 3;
        const int ky = ws - e * 3;
        __nv_bfloat16* WH = d_w2c_h + (long)ws * (3 * C2 * C1);
        __nv_bfloat16* WL = d_w2c_l + (long)ws * (3 * C2 * C1);
        for (int i = t; i < 3 * C2 * C1; i += 256) {
            const int kx  = i >> 13;           // / (128*64)
            const int rem = i & 8191;
            const int oc = rem >> 6, ch = rem & 63;
            const float w = e_conv2[(((long)(e * C2 + oc) * C1 + ch) * 9) + ky * 3 + kx];
            const __nv_bfloat16 h = __float2bfloat16(w);
            WH[i] = h;
            WL[i] = __float2bfloat16(w - __bfloat162float(h));
        }
    }
}

// ---------------------------------------------------------------------------
// Kernel 1: 7x7 s2 conv (15->64) via mma.sync + ldmatrix bf16x2.
// GATING=true : slot NE, BN affine + ReLU -> d_gbuf.
// GATING=false: slot d_eidx[b], ReLU -> d_c1out NHWC-64 deinterleaved bf16x2.
// ---------------------------------------------------------------------------
#define C1P      48
#define A_EV     0
#define A_OD     (132*C1P)
#define A_PL     (264*C1P)               // 12672 B per precision plane
#define B_OF     (2*A_PL)
#define B_PL     (448*C1P)               // 21504 B
#define CONV1_SMEM (2*A_PL + 2*B_PL)     // 68352 B

template <bool GATING>
__global__ void __launch_bounds__(256)
conv1_mma_kernel(const float* __restrict__ bn_gamma,
                 const float* __restrict__ bn_beta,
                 const float* __restrict__ bn_mean,
                 const float* __restrict__ bn_var)
{
    extern __shared__ __align__(16) char sm[];
    const int oy   = blockIdx.x;
    const int xh   = blockIdx.y;
    const int b    = blockIdx.z;
    const int t    = threadIdx.x;
    const int wid  = t >> 5;
    const int lane = t & 31;
    const int g    = lane >> 2;
    const int tg   = lane & 3;
    const int slot = GATING ? NE : d_eidx[b];
    const int pxbase = xh * 128;
    const int px0  = (wid & 3) * 32;
    const int och  = (wid >> 2) * 32;

    const uint32_t smb   = smem_u32(sm);
    const uint32_t aLane = (uint32_t)(lane & 15) * C1P + ((lane >> 4) * 16);
    const uint32_t bLane = (uint32_t)(lane & 7) * C1P + (((lane >> 3) & 1) * 16);

    float acc[2][4][4];
#pragma unroll
    for (int mt = 0; mt < 2; mt++)
#pragma unroll
        for (int nt = 0; nt < 4; nt++)
#pragma unroll
            for (int j = 0; j < 4; j++) acc[mt][nt][j] = 0.f;

#pragma unroll 1
    for (int ky = 0; ky < 7; ky++) {
        const int row = 2 * oy + ky;
        const __nv_bfloat16* sH = d_xnh_h + (long)(b * 520 + row) * (XNW * 16);
        const __nv_bfloat16* sL = d_xnh_l + (long)(b * 520 + row) * (XNW * 16);
        const uint4* eH = (const uint4*)(sH + (long)pxbase * 16);
        const uint4* eL = (const uint4*)(sL + (long)pxbase * 16);
        const uint4* oH = (const uint4*)(sH + (long)(pxbase + 260) * 16);
        const uint4* oL = (const uint4*)(sL + (long)(pxbase + 260) * 16);
        const uint4* wH = (const uint4*)(d_w1c_h + (long)(slot * 7 + ky) * (7 * C1 * 16));
        const uint4* wL = (const uint4*)(d_w1c_l + (long)(slot * 7 + ky) * (7 * C1 * 16));

        if (ky) __syncthreads();
        for (int i = t; i < 260; i += 256) {
            const int d0 = A_EV + (i >> 1) * C1P + ((i & 1) << 4);
            *(uint4*)(sm + d0)        = eH[i];
            *(uint4*)(sm + A_PL + d0) = eL[i];
        }
        for (int i = t; i < 262; i += 256) {
            const int d0 = A_OD + (i >> 1) * C1P + ((i & 1) << 4);
            *(uint4*)(sm + d0)        = oH[i];
            *(uint4*)(sm + A_PL + d0) = oL[i];
        }
        for (int i = t; i < 896; i += 256) {
            const int d0 = B_OF + (i >> 1) * C1P + ((i & 1) << 4);
            *(uint4*)(sm + d0)        = wH[i];
            *(uint4*)(sm + B_PL + d0) = wL[i];
        }
        __syncthreads();

#pragma unroll 1
        for (int kx = 0; kx < 7; kx++) {
            const uint32_t aoff = (kx & 1)
                ? (uint32_t)(A_EV + ((kx - 1) >> 1) * C1P)
                : (uint32_t)(A_OD + (kx >> 1) * C1P);
            const uint32_t aH0 = smb + aoff + (uint32_t)px0 * C1P + aLane;
            uint32_t AH[2][4], AL[2][4];
#pragma unroll
            for (int mt = 0; mt < 2; mt++) {
                ldm_x4(AH[mt], aH0 + (uint32_t)(mt * 16 * C1P));
                ldm_x4(AL[mt], aH0 + (uint32_t)(mt * 16 * C1P) + A_PL);
            }
#pragma unroll
            for (int nt = 0; nt < 4; nt++) {
                const uint32_t bAddr = smb + B_OF
                    + (uint32_t)(kx * 64 + och + nt * 8) * C1P + bLane;
                uint32_t BH0, BH1, BL0, BL1;
                ldm_x2(BH0, BH1, bAddr);
                ldm_x2(BL0, BL1, bAddr + B_PL);
#pragma unroll
                for (int mt = 0; mt < 2; mt++) {
                    mma_bf16(acc[mt][nt], AH[mt][0], AH[mt][1], AH[mt][2], AH[mt][3], BH0, BH1);
                    mma_bf16(acc[mt][nt], AH[mt][0], AH[mt][1], AH[mt][2], AH[mt][3], BL0, BL1);
                    mma_bf16(acc[mt][nt], AL[mt][0], AL[mt][1], AL[mt][2], AL[mt][3], BH0, BH1);
                }
            }
        }
    }

    if (GATING) {
#pragma unroll
        for (int nt = 0; nt < 4; nt++) {
            const int oc0 = och + nt * 8 + 2 * tg;
            const int oc1 = oc0 + 1;
            const float s0 = bn_gamma[oc0] * rsqrtf(bn_var[oc0] + 1e-5f);
            const float s1 = bn_gamma[oc1] * rsqrtf(bn_var[oc1] + 1e-5f);
            const float t0 = bn_beta[oc0] - bn_mean[oc0] * s0;
            const float t1 = bn_beta[oc1] - bn_mean[oc1] * s1;
            float* b0 = d_gbuf + ((long)(b * C1 + oc0) * H1 + oy) * W1;
            float* b1 = d_gbuf + ((long)(b * C1 + oc1) * H1 + oy) * W1;
#pragma unroll
            for (int mt = 0; mt < 2; mt++) {
                const int px = pxbase + px0 + mt * 16 + g;
                b0[px]     = fmaxf(acc[mt][nt][0] * s0 + t0, 0.f);
                b1[px]     = fmaxf(acc[mt][nt][1] * s1 + t1, 0.f);
                b0[px + 8] = fmaxf(acc[mt][nt][2] * s0 + t0, 0.f);
                b1[px + 8] = fmaxf(acc[mt][nt][3] * s1 + t1, 0.f);
            }
        }
    } else {
        // ReLU -> NHWC-64 deinterleaved bf16x2 (even pos px/2, odd 129+px/2)
#pragma unroll
        for (int nt = 0; nt < 4; nt++) {
            const int oc0 = och + nt * 8 + 2 * tg;
#pragma unroll
            for (int mt = 0; mt < 2; mt++) {
                const int px  = pxbase + px0 + mt * 16 + g;
                const int pos = (px & 1) ? (129 + (px >> 1)) : (px >> 1);
                const long base = ((long)(b * C1R + (oy + 1)) * C1WP + pos) * C1 + oc0;
                uint32_t hi, lo;
                split2(fmaxf(acc[mt][nt][0], 0.f), fmaxf(acc[mt][nt][1], 0.f), hi, lo);
                *(uint32_t*)(d_c1out_h + base) = hi;
                *(uint32_t*)(d_c1out_l + base) = lo;
                split2(fmaxf(acc[mt][nt][2], 0.f), fmaxf(acc[mt][nt][3], 0.f), hi, lo);
                *(uint32_t*)(d_c1out_h + base + 4 * C1) = hi;   // px+8 -> pos+4
                *(uint32_t*)(d_c1out_l + base + 4 * C1) = lo;
            }
        }
    }
}

// ---------------------------------------------------------------------------
// Kernel 2: maxpool 3x3 s2 pad1 + spatial mean, per (b,c).
// ---------------------------------------------------------------------------
__global__ void pool_mean_kernel()
{
    const int bc = blockIdx.x;
    const float* p = d_gbuf + (long)bc * (H1 * W1);
    float sum = 0.f;
    for (int i = threadIdx.x; i < H2 * W2; i += blockDim.x) {
        const int py = i >> 7, px = i & 127;
        float m = -1e30f;
#pragma unroll
        for (int dy = 0; dy < 3; dy++) {
            const int iy = py * 2 - 1 + dy;
            if ((unsigned)iy >= (unsigned)H1) continue;
            const float* row = p + iy * W1;
#pragma unroll
            for (int dx = 0; dx < 3; dx++) {
                const int ix = px * 2 - 1 + dx;
                if ((unsigned)ix < (unsigned)W1) m = fmaxf(m, row[ix]);
            }
        }
        sum += m;
    }
    __shared__ float red[256];
    red[threadIdx.x] = sum;
    __syncthreads();
    for (int s = 128; s > 0; s >>= 1) {
        if (threadIdx.x < s) red[threadIdx.x] += red[threadIdx.x + s];
        __syncthreads();
    }
    if (threadIdx.x == 0) d_pooled[bc] = red[0] * (1.f / (H2 * W2));
}

// ---------------------------------------------------------------------------
// Kernel 3: FC -> logits -> top-1 expert + aux loss.
// ---------------------------------------------------------------------------
__global__ void gate_finalize_kernel(const float* __restrict__ fcw,
                                     const float* __restrict__ fcb,
                                     float* __restrict__ out_loss)
{
    __shared__ float logits[B][NE];
    const int t = threadIdx.x;
    if (t < B * NE) {
        const int b = t / NE, e = t % NE;
        float s = fcb[e];
        const float* pw = fcw + e * C1;
        const float* pp = d_pooled + b * C1;
        for (int i = 0; i < C1; i++) s += pp[i] * pw[i];
        logits[b][e] = s;
    }
    __syncthreads();
    if (t == 0) {
        float dens[NE]  = {0.f, 0.f, 0.f};
        float proxy[NE] = {0.f, 0.f, 0.f};
        for (int b = 0; b < B; b++) {
            int bi = 0;
            for (int e = 1; e < NE; e++)
                if (logits[b][e] > logits[b][bi]) bi = e;
            d_eidx[b] = bi;
            dens[bi] += 1.f / B;
            float mx = logits[b][0];
            for (int e = 1; e < NE; e++) mx = fmaxf(mx, logits[b][e]);
            float ex[NE], sum = 0.f;
            for (int e = 0; e < NE; e++) { ex[e] = expf(logits[b][e] - mx); sum += ex[e]; }
            for (int e = 0; e < NE; e++) proxy[e] += ex[e] / sum * (1.f / B);
        }
        float aux = 0.f;
        for (int e = 0; e < NE; e++) aux += dens[e] * proxy[e];
        *out_loss = 0.01f * aux * (float)NE;
    }
}

// ---------------------------------------------------------------------------
// Kernel 4: expert conv2 (3x3 s2, 64->128) via mma.sync + ldmatrix bf16x2.
// Grid (128 rows, 8 b), 256 thr = 8 warps (4 px-tiles x 2 oc-halves).
// Per ky: stage A even(128)+odd(129) rows + B (3 kx x 128 oc) at 144B pitch.
// Epilogue: ReLU -> NHWC act bf16x2 (head1 input, unchanged layout).
// ---------------------------------------------------------------------------
#define C2P      144
#define C2_AEV   0
#define C2_AOD   (128*C2P)
#define C2_APL   (260*C2P)               // 37440 B per precision plane
#define C2_BOF   (2*C2_APL)
#define C2_BPL   (384*C2P)               // 55296 B
#define CONV2_SMEM (2*C2_APL + 2*C2_BPL) // 185472 B

__global__ void __launch_bounds__(256)
conv2_mma_kernel()
{
    extern __shared__ __align__(16) char sm[];
    const int oy   = blockIdx.x;          // output row 0..127
    const int b    = blockIdx.y;
    const int t    = threadIdx.x;
    const int wid  = t >> 5;
    const int lane = t & 31;
    const int g    = lane >> 2;
    const int tg   = lane & 3;
    const int e    = d_eidx[b];
    const int px0  = (wid & 3) * 32;
    const int ocq  = (wid >> 2) * 64;

    const uint32_t smb   = smem_u32(sm);
    const uint32_t aLane = (uint32_t)(lane & 15) * C2P + ((lane >> 4) * 16);
    const uint32_t bLane = (uint32_t)(lane & 7) * C2P + (((lane >> 3) & 1) * 16);

    float acc[2][8][4];
#pragma unroll
    for (int mt = 0; mt < 2; mt++)
#pragma unroll
        for (int nt = 0; nt < 8; nt++)
#pragma unroll
            for (int j = 0; j < 4; j++) acc[mt][nt][j] = 0.f;

#pragma unroll 1
    for (int ky = 0; ky < 3; ky++) {
        const int row = 2 * oy + ky;      // padded row (iy+1), 0..256
        const __nv_bfloat16* sH = d_c1out_h + (long)(b * C1R + row) * (C1WP * C1);
        const __nv_bfloat16* sL = d_c1out_l + (long)(b * C1R + row) * (C1WP * C1);
        const uint4* eH = (const uint4*)sH;                    // even pos 0..127
        const uint4* eL = (const uint4*)sL;
        const uint4* oH = (const uint4*)(sH + (long)128 * C1); // odd pos 128..256
        const uint4* oL = (const uint4*)(sL + (long)128 * C1);
        const uint4* wH = (const uint4*)(d_w2c_h + (long)(e * 3 + ky) * (3 * C2 * C1));
        const uint4* wL = (const uint4*)(d_w2c_l + (long)(e * 3 + ky) * (3 * C2 * C1));

        if (ky) __syncthreads();
        // A even: 128 rows x 128B = 1024 16B-chunks per plane
        for (int i = t; i < 1024; i += 256) {
            const int d0 = C2_AEV + (i >> 3) * C2P + ((i & 7) << 4);
            *(uint4*)(sm + d0)           = eH[i];
            *(uint4*)(sm + C2_APL + d0)  = eL[i];
        }
        // A odd: 129 rows = 1032 chunks
        for (int i = t; i < 1032; i += 256) {
            const int d0 = C2_AOD + (i >> 3) * C2P + ((i & 7) << 4);
            *(uint4*)(sm + d0)           = oH[i];
            *(uint4*)(sm + C2_APL + d0)  = oL[i];
        }
        // B: 384 rows = 3072 chunks
        for (int i = t; i < 3072; i += 256) {
            const int d0 = C2_BOF + (i >> 3) * C2P + ((i & 7) << 4);
            *(uint4*)(sm + d0)           = wH[i];
            *(uint4*)(sm + C2_BPL + d0)  = wL[i];
        }
        __syncthreads();

#pragma unroll 1
        for (int kx = 0; kx < 3; kx++) {
            // kx=1 -> even row px; kx=0 -> odd row px; kx=2 -> odd row px+1
            const uint32_t aoff = (kx == 1) ? (uint32_t)C2_AEV
                                : (kx == 0) ? (uint32_t)C2_AOD
                                            : (uint32_t)(C2_AOD + C2P);
            const uint32_t aH0 = smb + aoff + (uint32_t)px0 * C2P + aLane;
#pragma unroll
            for (int ks = 0; ks < 4; ks++) {
                const uint32_t ko = (uint32_t)(32 * ks);
                uint32_t AH[2][4], AL[2][4];
#pragma unroll
                for (int mt = 0; mt < 2; mt++) {
                    ldm_x4(AH[mt], aH0 + ko + (uint32_t)(mt * 16 * C2P));
                    ldm_x4(AL[mt], aH0 + ko + (uint32_t)(mt * 16 * C2P) + C2_APL);
                }
#pragma unroll
                for (int nt = 0; nt < 8; nt++) {
                    const uint32_t bAddr = smb + C2_BOF
                        + (uint32_t)(kx * C2 + ocq + nt * 8) * C2P + bLane + ko;
                    uint32_t BH0, BH1, BL0, BL1;
                    ldm_x2(BH0, BH1, bAddr);
                    ldm_x2(BL0, BL1, bAddr + C2_BPL);
#pragma unroll
                    for (int mt = 0; mt < 2; mt++) {
                        mma_bf16(acc[mt][nt], AH[mt][0], AH[mt][1], AH[mt][2], AH[mt][3], BH0, BH1);
                        mma_bf16(acc[mt][nt], AH[mt][0], AH[mt][1], AH[mt][2], AH[mt][3], BL0, BL1);
                        mma_bf16(acc[mt][nt], AL[mt][0], AL[mt][1], AL[mt][2], AL[mt][3], BH0, BH1);
                    }
                }
            }
        }
    }

    // Epilogue: ReLU -> NHWC act bf16x2 at [b][oy+1][px+1][oc]
#pragma unroll
    for (int nt = 0; nt < 8; nt++) {
        const int oc0 = ocq + nt * 8 + 2 * tg;
#pragma unroll
        for (int mt = 0; mt < 2; mt++) {
            const int px = px0 + mt * 16 + g;
            const long off = (((long)b * AR + (oy + 1)) * AW + (px + 1)) * C2 + oc0;
            uint32_t hi, lo;
            split2(fmaxf(acc[mt][nt][0], 0.f), fmaxf(acc[mt][nt][1], 0.f), hi, lo);
            *(uint32_t*)(d_act_hi + off) = hi;
            *(uint32_t*)(d_act_lo + off) = lo;
            split2(fmaxf(acc[mt][nt][2], 0.f), fmaxf(acc[mt][nt][3], 0.f), hi, lo);
            *(uint32_t*)(d_act_hi + off + 8 * C2) = hi;   // px+8
            *(uint32_t*)(d_act_lo + off + 8 * C2) = lo;
        }
    }
}

// ---------------------------------------------------------------------------
// Kernel 5: head1 via mma.sync bf16x2 + smem staging + ldmatrix (proven)
// ---------------------------------------------------------------------------
#define PITCHB   272
#define TILE_B   (128 * PITCHB)
#define OFF_AH   0
#define OFF_AL   TILE_B
#define OFF_BH   (2 * TILE_B)
#define OFF_BL   (3 * TILE_B)
#define HEAD1_SMEM (4 * TILE_B)

__global__ void __launch_bounds__(256)
head1_mma_kernel(const float* __restrict__ b_all)
{
    extern __shared__ __align__(16) char sm[];
    const int oy   = blockIdx.x;
    const int b    = blockIdx.y;
    const int t    = threadIdx.x;
    const int wid  = t >> 5;
    const int lane = t & 31;
    const int g    = lane >> 2;
    const int tg   = lane & 3;
    const int e    = d_eidx[b];
    const int px0  = (wid & 3) * 32;
    const int ocq  = (wid >> 2) * 64;

    const uint32_t smb = smem_u32(sm);
    const uint32_t aRow = (uint32_t)(px0 + (lane & 15)) * PITCHB + ((lane >> 4) * 16);
    const uint32_t bRow = (uint32_t)(ocq + (lane & 7)) * PITCHB + (((lane >> 3) & 1) * 16);
    const uint32_t aAH0 = smb + OFF_AH + aRow;
    const uint32_t aAL0 = smb + OFF_AL + aRow;
    const uint32_t aBH0 = smb + OFF_BH + bRow;
    const uint32_t aBL0 = smb + OFF_BL + bRow;

    float acc[2][8][4];
#pragma unroll
    for (int mt = 0; mt < 2; mt++)
#pragma unroll
        for (int nt = 0; nt < 8; nt++)
#pragma unroll
            for (int j = 0; j < 4; j++) acc[mt][nt][j] = 0.f;

#pragma unroll 1
    for (int s = 0; s < 9; s++) {
        const int dy = s / 3, dx = s - 3 * dy;
        const uint4* srcAH = (const uint4*)(d_act_hi + (((long)b * AR + (oy + dy)) * AW + dx) * C2);
        const uint4* srcAL = (const uint4*)(d_act_lo + (((long)b * AR + (oy + dy)) * AW + dx) * C2);
        const uint4* srcBH = (const uint4*)(d_w1h + (long)(e * 9 + s) * (C2 * C2));
        const uint4* srcBL = (const uint4*)(d_w1l + (long)(e * 9 + s) * (C2 * C2));

        if (s) __syncthreads();
#pragma unroll 1
        for (int idx = t; idx < 2048; idx += 256) {
            const int row = idx >> 4, ch = idx & 15;
            const int d0  = row * PITCHB + (ch << 4);
            *(uint4*)(sm + OFF_AH + d0) = srcAH[idx];
            *(uint4*)(sm + OFF_AL + d0) = srcAL[idx];
            *(uint4*)(sm + OFF_BH + d0) = srcBH[idx];
            *(uint4*)(sm + OFF_BL + d0) = srcBL[idx];
        }
        __syncthreads();

#pragma unroll 1
        for (int ks = 0; ks < 8; ks++) {
            const uint32_t ko = (uint32_t)(32 * ks);
            uint32_t AH[2][4], AL[2][4];
#pragma unroll
            for (int mt = 0; mt < 2; mt++) {
                ldm_x4(AH[mt], aAH0 + ko + (uint32_t)(mt * 16 * PITCHB));
                ldm_x4(AL[mt], aAL0 + ko + (uint32_t)(mt * 16 * PITCHB));
            }
#pragma unroll
            for (int nt = 0; nt < 8; nt++) {
                uint32_t BH0, BH1, BL0, BL1;
                ldm_x2(BH0, BH1, aBH0 + ko + (uint32_t)(nt * 8 * PITCHB));
                ldm_x2(BL0, BL1, aBL0 + ko + (uint32_t)(nt * 8 * PITCHB));
#pragma unroll
                for (int mt = 0; mt < 2; mt++) {
                    mma_bf16(acc[mt][nt], AH[mt][0], AH[mt][1], AH[mt][2], AH[mt][3], BH0, BH1);
                    mma_bf16(acc[mt][nt], AH[mt][0], AH[mt][1], AH[mt][2], AH[mt][3], BL0, BL1);
                    mma_bf16(acc[mt][nt], AL[mt][0], AL[mt][1], AL[mt][2], AL[mt][3], BH0, BH1);
                }
            }
        }
    }

#pragma unroll
    for (int nt = 0; nt < 8; nt++) {
        const int oc0 = ocq + nt * 8 + 2 * tg;
        const float bias0 = b_all[e * C2 + oc0];
        const float bias1 = b_all[e * C2 + oc0 + 1];
        float* o0 = d_ebuf3 + ((long)(b * C2 + oc0) * H2 + oy) * W2;
        float* o1 = d_ebuf3 + ((long)(b * C2 + oc0 + 1) * H2 + oy) * W2;
#pragma unroll
        for (int mt = 0; mt < 2; mt++) {
            const int px = px0 + mt * 16 + g;
            o0[px]     = fmaxf(acc[mt][nt][0] + bias0, 0.f);
            o1[px]     = fmaxf(acc[mt][nt][1] + bias1, 0.f);
            o0[px + 8] = fmaxf(acc[mt][nt][2] + bias0, 0.f);
            o1[px + 8] = fmaxf(acc[mt][nt][3] + bias1, 0.f);
        }
    }
}

// ---------------------------------------------------------------------------
// Kernel 6: 1x1 conv 128 -> 5 + bias, scatter into (hm, wh, reg) layout.
// ---------------------------------------------------------------------------
__global__ void __launch_bounds__(128)
head2_kernel(const float* __restrict__ w_all,
             const float* __restrict__ b_all,
             float* __restrict__ out)
{
    const int oy = blockIdx.x;
    const int b  = blockIdx.y;
    const int ox = threadIdx.x;
    const int e  = d_eidx[b];

    __shared__ __align__(16) float ws[C2][8];
    for (int idx = threadIdx.x; idx < 5 * C2; idx += 128) {
        const int j = idx / C2, ic = idx - j * C2;
        ws[ic][j] = w_all[(long)e * 5 * C2 + idx];
    }
    __syncthreads();

    float acc[5] = {0.f, 0.f, 0.f, 0.f, 0.f};
    const float* ib = d_ebuf3 + (long)b * C2 * H2 * W2 + oy * W2 + ox;
    for (int ic = 0; ic < C2; ic++) {
        const float v = __ldg(ib + ic * (H2 * W2));
        const float4 w4 = *(const float4*)ws[ic];
        acc[0] += v * w4.x;
        acc[1] += v * w4.y;
        acc[2] += v * w4.z;
        acc[3] += v * w4.w;
        acc[4] += v * ws[ic][4];
    }

    const int p  = oy * W2 + ox;
    const int HW = H2 * W2;
    const float* bb = b_all + e * 5;
    out[b * HW + p]                        = acc[0] + bb[0];
    out[B * HW + (b * 2 + 0) * HW + p]     = acc[1] + bb[1];
    out[B * HW + (b * 2 + 1) * HW + p]     = acc[2] + bb[2];
    out[3 * B * HW + (b * 2 + 0) * HW + p] = acc[3] + bb[3];
    out[3 * B * HW + (b * 2 + 1) * HW + p] = acc[4] + bb[4];
}

// ---------------------------------------------------------------------------
// Launch
// ---------------------------------------------------------------------------
extern "C" void kernel_launch(void* const* d_in, const int* in_sizes, int n_in,
                              void* d_out, int out_size)
{
    const float* x        = (const float*)d_in[0];
    const float* g_conv_w = (const float*)d_in[1];
    const float* g_gamma  = (const float*)d_in[2];
    const float* g_beta   = (const float*)d_in[3];
    const float* g_mean   = (const float*)d_in[4];
    const float* g_var    = (const float*)d_in[5];
    const float* g_fc_w   = (const float*)d_in[6];
    const float* g_fc_b   = (const float*)d_in[7];
    const float* e_conv1  = (const float*)d_in[8];
    const float* e_conv2  = (const float*)d_in[9];
    const float* e_hw1    = (const float*)d_in[10];
    const float* e_hb1    = (const float*)d_in[11];
    const float* e_hw2    = (const float*)d_in[12];
    const float* e_hb2    = (const float*)d_in[13];
    float* out = (float*)d_out;

    cudaFuncSetAttribute(head1_mma_kernel,
                         cudaFuncAttributeMaxDynamicSharedMemorySize,
                         HEAD1_SMEM);
    cudaFuncSetAttribute(conv1_mma_kernel<true>,
                         cudaFuncAttributeMaxDynamicSharedMemorySize,
                         CONV1_SMEM);
    cudaFuncSetAttribute(conv1_mma_kernel<false>,
                         cudaFuncAttributeMaxDynamicSharedMemorySize,
                         CONV1_SMEM);
    cudaFuncSetAttribute(conv2_mma_kernel,
                         cudaFuncAttributeMaxDynamicSharedMemorySize,
                         CONV2_SMEM);

    // 0. Layout prep (NHWC-16 input, halos, weight splits)
    prep_kernel<<<PREP_W2, 256>>>(x, e_hw1, e_conv1, g_conv_w, e_conv2);
    // 1. Gating conv (7x7 s2) via mma.sync bf16x2 + BN + ReLU -> gbuf
    conv1_mma_kernel<true><<<dim3(256, 2, B), 256, CONV1_SMEM>>>(g_gamma, g_beta, g_mean, g_var);
    // 2. Maxpool + global average
    pool_mean_kernel<<<B * C1, 256>>>();
    // 3. Logits, top-1 expert selection, aux loss
    gate_finalize_kernel<<<1, 32>>>(g_fc_w, g_fc_b, out + (out_size - 1));
    // 4. Expert conv1 (7x7 s2) via mma.sync bf16x2 -> c1out NHWC-64 bf16x2
    conv1_mma_kernel<false><<<dim3(256, 2, B), 256, CONV1_SMEM>>>(nullptr, nullptr, nullptr, nullptr);
    // 5. Expert conv2 (3x3 s2) via mma.sync bf16x2 -> NHWC act bf16x2
    conv2_mma_kernel<<<dim3(H2, B), 256, CONV2_SMEM>>>();
    // 6. Head conv1 via mma.sync + ldmatrix bf16x2 -> ebuf3
    head1_mma_kernel<<<dim3(H2, B), 256, HEAD1_SMEM>>>(e_hb1);
    // 7. Head conv2 (1x1) + bias, scattered to (hm, wh, reg)
    head2_kernel<<<dim3(128, B), 128>>>(e_hw2, e_hb2, out);
}